// round 3
// baseline (speedup 1.0000x reference)
#include <cuda_runtime.h>
#include <math.h>

#define NN 100000
#define EE 1600000
#define FD 128

// ---------------- scratch (device globals: allocation-free) ----------------
__device__ int   g_off[NN + 1];
__device__ int   g_cur[NN];
__device__ int   g_src[EE];
__device__ float g_attr[EE];
__device__ float g_xsrc[(size_t)NN * FD];
__device__ float g_xdst[(size_t)NN * FD];

// ---------------- small helpers: packed f32x2 FMA (sm_103a) ----------------
__device__ __forceinline__ unsigned long long pk(float lo, float hi) {
    unsigned long long r;
    asm("mov.b64 %0, {%1, %2};" : "=l"(r) : "f"(lo), "f"(hi));
    return r;
}
__device__ __forceinline__ unsigned long long ffma2(unsigned long long a,
                                                    unsigned long long b,
                                                    unsigned long long c) {
    unsigned long long d;
    asm("fma.rn.f32x2 %0, %1, %2, %3;" : "=l"(d) : "l"(a), "l"(b), "l"(c));
    return d;
}
__device__ __forceinline__ float2 upk(unsigned long long v) {
    float lo, hi;
    asm("mov.b64 {%0, %1}, %2;" : "=f"(lo), "=f"(hi) : "l"(v));
    return make_float2(lo, hi);
}

// ---------------- CSR build ----------------
__global__ void k_zero() {
    int i = blockIdx.x * blockDim.x + threadIdx.x;
    if (i < NN) g_cur[i] = 0;
}

__global__ void k_hist(const int* __restrict__ ei) {
    int e = blockIdx.x * blockDim.x + threadIdx.x;
    if (e < EE) atomicAdd(&g_cur[ei[EE + e]], 1);
}

// single-block exclusive scan over N=100000 (1024 threads, chunked)
__global__ void k_scan() {
    __shared__ int wsum[32];
    int tid = threadIdx.x, lane = tid & 31, wid = tid >> 5;
    int carry = 0;
    for (int base = 0; base < NN; base += 1024) {
        int i = base + tid;
        int v = (i < NN) ? g_cur[i] : 0;
        int xv = v;
#pragma unroll
        for (int off = 1; off < 32; off <<= 1) {
            int y = __shfl_up_sync(0xffffffffu, xv, off);
            if (lane >= off) xv += y;
        }
        if (lane == 31) wsum[wid] = xv;
        __syncthreads();
        if (wid == 0) {
            int s = wsum[lane];
#pragma unroll
            for (int off = 1; off < 32; off <<= 1) {
                int y = __shfl_up_sync(0xffffffffu, s, off);
                if (lane >= off) s += y;
            }
            wsum[lane] = s;
        }
        __syncthreads();
        int wpre = wid ? wsum[wid - 1] : 0;
        int excl = carry + wpre + xv - v;
        if (i < NN) { g_off[i] = excl; g_cur[i] = excl; }
        carry += wsum[31];
        __syncthreads();
    }
    if (tid == 0) g_off[NN] = carry;
}

__global__ void k_fill(const int* __restrict__ ei, const float* __restrict__ ea) {
    int e = blockIdx.x * blockDim.x + threadIdx.x;
    if (e < EE) {
        int d = ei[EE + e];
        int p = atomicAdd(&g_cur[d], 1);
        g_src[p]  = ei[e];
        g_attr[p] = ea[e];
    }
}

// ---------------- GEMM: out[i][o] = sum_k x[i][k] * W[k][o] + bias[o] -------
// 128x128 output tile per block, 256 threads, 8x8 outputs/thread, packed f32x2.
__global__ void k_gemm(const float* __restrict__ X, const float* __restrict__ W,
                       const float* __restrict__ Bias, int which) {
    extern __shared__ float sm[];
    float* As = sm;              // [128][128] row-major (row, k)
    float* Bs = sm + 128 * 128;  // [128][128] (k, col)
    float* outp = which ? g_xdst : g_xsrc;

    int tid  = threadIdx.x;
    int row0 = blockIdx.x * 128;
    int c4   = (tid & 31) * 4;
    int rr   = tid >> 5;
#pragma unroll
    for (int i = 0; i < 16; i++) {
        int r  = rr + i * 8;
        int gr = row0 + r;
        float4 v = make_float4(0.f, 0.f, 0.f, 0.f);
        if (gr < NN) v = *(const float4*)(X + (size_t)gr * FD + c4);
        *(float4*)(As + r * 128 + c4) = v;
        *(float4*)(Bs + r * 128 + c4) = *(const float4*)(W + r * 128 + c4);
    }
    __syncthreads();

    int tx = tid & 15, ty = tid >> 4;
    int r0 = ty * 8, c0 = tx * 8;
    unsigned long long acc[8][4];
#pragma unroll
    for (int j = 0; j < 8; j++)
#pragma unroll
        for (int c = 0; c < 4; c++) acc[j][c] = 0ull;

#pragma unroll 4
    for (int k = 0; k < 128; k++) {
        float4 b0 = *(float4*)(Bs + k * 128 + c0);
        float4 b1 = *(float4*)(Bs + k * 128 + c0 + 4);
        unsigned long long bb0 = pk(b0.x, b0.y);
        unsigned long long bb1 = pk(b0.z, b0.w);
        unsigned long long bb2 = pk(b1.x, b1.y);
        unsigned long long bb3 = pk(b1.z, b1.w);
#pragma unroll
        for (int j = 0; j < 8; j++) {
            float a = As[(r0 + j) * 128 + k];
            unsigned long long a2 = pk(a, a);
            acc[j][0] = ffma2(a2, bb0, acc[j][0]);
            acc[j][1] = ffma2(a2, bb1, acc[j][1]);
            acc[j][2] = ffma2(a2, bb2, acc[j][2]);
            acc[j][3] = ffma2(a2, bb3, acc[j][3]);
        }
    }

#pragma unroll
    for (int j = 0; j < 8; j++) {
        int gr = row0 + r0 + j;
        if (gr < NN) {
            float2 p0 = upk(acc[j][0]), p1 = upk(acc[j][1]);
            float2 p2 = upk(acc[j][2]), p3 = upk(acc[j][3]);
            float4 o0, o1;
            o0.x = p0.x + Bias[c0 + 0]; o0.y = p0.y + Bias[c0 + 1];
            o0.z = p1.x + Bias[c0 + 2]; o0.w = p1.y + Bias[c0 + 3];
            o1.x = p2.x + Bias[c0 + 4]; o1.y = p2.y + Bias[c0 + 5];
            o1.z = p3.x + Bias[c0 + 6]; o1.w = p3.y + Bias[c0 + 7];
            *(float4*)(outp + (size_t)gr * FD + c0)     = o0;
            *(float4*)(outp + (size_t)gr * FD + c0 + 4) = o1;
        }
    }
}

// ---------------- fused attention aggregation (one warp per dst node) -------
// Online softmax over incoming edges; single gather of x_src[src] per edge.
// Lane l owns features 4l..4l+3 (head h = l>>2). Then LayerNorm+ELU+residual.
__global__ void k_agg(const float* __restrict__ x,
                      const float* __restrict__ Wedge,
                      const float* __restrict__ att,
                      const float* __restrict__ bias,
                      const float* __restrict__ gamma,
                      const float* __restrict__ beta,
                      float* __restrict__ out) {
    int node = (int)((blockIdx.x * blockDim.x + threadIdx.x) >> 5);
    int lane = threadIdx.x & 31;
    if (node >= NN) return;

    int beg = g_off[node], end = g_off[node + 1];

    const float4 xd = *(const float4*)(g_xdst + (size_t)node * FD + lane * 4);
    const float4 we = *(const float4*)(Wedge + lane * 4);
    const float4 at = *(const float4*)(att + lane * 4);

    float m = -INFINITY;
    float denom = 0.f;
    float4 acc = make_float4(0.f, 0.f, 0.f, 0.f);

    for (int p = beg; p < end; p++) {
        int   s  = g_src[p];
        float ea = g_attr[p];
        float4 a = *(const float4*)(g_xsrc + (size_t)s * FD + lane * 4);

        float hx = a.x + xd.x + ea * we.x;
        float hy = a.y + xd.y + ea * we.y;
        float hz = a.z + xd.z + ea * we.z;
        float hw = a.w + xd.w + ea * we.w;
        hx = hx > 0.f ? hx : 0.2f * hx;
        hy = hy > 0.f ? hy : 0.2f * hy;
        hz = hz > 0.f ? hz : 0.2f * hz;
        hw = hw > 0.f ? hw : 0.2f * hw;

        float part = hx * at.x + hy * at.y + hz * at.z + hw * at.w;
        part += __shfl_xor_sync(0xffffffffu, part, 1);
        part += __shfl_xor_sync(0xffffffffu, part, 2);  // head logit (4-lane group)

        float mn = fmaxf(m, part);
        float sc = __expf(m - mn);        // m = -inf initially -> 0
        float w  = __expf(part - mn);
        denom = denom * sc + w;
        acc.x = acc.x * sc + w * a.x;
        acc.y = acc.y * sc + w * a.y;
        acc.z = acc.z * sc + w * a.z;
        acc.w = acc.w * sc + w * a.w;
        m = mn;
    }

    float inv = (denom > 0.f) ? (1.0f / denom) : 0.f;
    const float4 bi = *(const float4*)(bias + lane * 4);
    float4 o;
    o.x = acc.x * inv + bi.x;
    o.y = acc.y * inv + bi.y;
    o.z = acc.z * inv + bi.z;
    o.w = acc.w * inv + bi.w;

    // LayerNorm over the 128 features held by this warp
    float s1 = o.x + o.y + o.z + o.w;
    float s2 = o.x * o.x + o.y * o.y + o.z * o.z + o.w * o.w;
#pragma unroll
    for (int off = 16; off > 0; off >>= 1) {
        s1 += __shfl_xor_sync(0xffffffffu, s1, off);
        s2 += __shfl_xor_sync(0xffffffffu, s2, off);
    }
    float mu   = s1 * (1.f / 128.f);
    float var  = s2 * (1.f / 128.f) - mu * mu;
    float rstd = rsqrtf(var + 1e-5f);

    const float4 ga = *(const float4*)(gamma + lane * 4);
    const float4 be = *(const float4*)(beta + lane * 4);
    const float4 xi = *(const float4*)(x + (size_t)node * FD + lane * 4);

    float4 r;
    r.x = (o.x - mu) * rstd * ga.x + be.x;
    r.y = (o.y - mu) * rstd * ga.y + be.y;
    r.z = (o.z - mu) * rstd * ga.z + be.z;
    r.w = (o.w - mu) * rstd * ga.w + be.w;
    r.x = (r.x > 0.f ? r.x : __expf(r.x) - 1.f) + xi.x;
    r.y = (r.y > 0.f ? r.y : __expf(r.y) - 1.f) + xi.y;
    r.z = (r.z > 0.f ? r.z : __expf(r.z) - 1.f) + xi.z;
    r.w = (r.w > 0.f ? r.w : __expf(r.w) - 1.f) + xi.w;

    *(float4*)(out + (size_t)node * FD + lane * 4) = r;
}

// ---------------- launch ----------------
extern "C" void kernel_launch(void* const* d_in, const int* in_sizes, int n_in,
                              void* d_out, int out_size) {
    const float* x    = (const float*)d_in[0];
    const int*   ei   = (const int*)  d_in[1];
    const float* ea   = (const float*)d_in[2];
    const float* Wsrc = (const float*)d_in[3];
    const float* bsrc = (const float*)d_in[4];
    const float* Wdst = (const float*)d_in[5];
    const float* bdst = (const float*)d_in[6];
    const float* Wed  = (const float*)d_in[7];
    const float* att  = (const float*)d_in[8];
    const float* bias = (const float*)d_in[9];
    const float* gam  = (const float*)d_in[10];
    const float* bet  = (const float*)d_in[11];
    float* out = (float*)d_out;

    cudaFuncSetAttribute(k_gemm, cudaFuncAttributeMaxDynamicSharedMemorySize, 131072);

    k_zero<<<(NN + 255) / 256, 256>>>();
    k_hist<<<(EE + 255) / 256, 256>>>(ei);
    k_scan<<<1, 1024>>>();
    k_fill<<<(EE + 255) / 256, 256>>>(ei, ea);
    k_gemm<<<(NN + 127) / 128, 256, 131072>>>(x, Wsrc, bsrc, 0);
    k_gemm<<<(NN + 127) / 128, 256, 131072>>>(x, Wdst, bdst, 1);
    k_agg<<<(NN + 7) / 8, 256>>>(x, Wed, att, bias, gam, bet, out);
}